// round 2
// baseline (speedup 1.0000x reference)
#include <cuda_runtime.h>
#include <cuda_bf16.h>
#include <math.h>

// Problem dims
#define BN   128
#define TT   800
#define UU   64
#define HH   256
#define KMIX 10
#define GG   20
#define AA   64

#define NBLK 128
#define NTHR 256
#define KT1  323   // 3 + 64 + 256
#define KT2  579   // 3 + 64 + 256 + 256
#define SMEM_FLOATS (32*KT2 + 32*32)
#define SMEM_BYTES  (SMEM_FLOATS*4)

// -------- persistent state (device globals; zero-init at module load) --------
__device__ float g_h1[2][BN*HH];
__device__ float g_h2[2][BN*HH];
__device__ float g_c1[BN*HH];
__device__ float g_c2[BN*HH];
__device__ float g_c3[BN*HH];
__device__ float g_w[BN*AA];
__device__ float g_kappa[BN*KMIX];
__device__ float g_zero[BN*HH];          // never written: h3 state at t=-1
__device__ float g_out_h3[(size_t)TT*BN*HH];

__device__ unsigned g_bar_cnt;
__device__ volatile unsigned g_bar_gen;

// -------- software grid barrier (all 128 CTAs resident on 148 SMs) ----------
__device__ __forceinline__ void grid_barrier() {
    __syncthreads();
    if (threadIdx.x == 0) {
        unsigned gen = g_bar_gen;
        __threadfence();   // release (emits CCTL.IVALL -> L1D flush, gpu scope)
        if (atomicAdd(&g_bar_cnt, 1u) == (unsigned)(gridDim.x - 1u)) {
            g_bar_cnt = 0u;
            __threadfence();
            g_bar_gen = gen + 1u;
        } else {
            while (g_bar_gen == gen) { }
        }
        __threadfence();   // acquire
    }
    __syncthreads();
}

__device__ __forceinline__ float sigmoidf_(float v) { return 1.0f / (1.0f + expf(-v)); }

// -------- load the 32-row X tile (concat pieces) into shared -----------------
// layout per row: [x(3) | w(64) | (lower 256 if KIN==323) | hrec(256)]
template<int KIN>
__device__ __forceinline__ void load_rows(float* sX, const float* __restrict__ x, int t,
                                          const float* __restrict__ wv,
                                          const float* __restrict__ lower,
                                          const float* __restrict__ hrec, int bb) {
    const int Ktot = KIN + 256;
    int warp = threadIdx.x >> 5, lane = threadIdx.x & 31;
    for (int r = warp; r < 32; r += 8) {
        int brow = bb * 32 + r;
        float* dst = sX + r * Ktot;
        if (lane < 3) dst[lane] = x[brow * (TT*3) + t*3 + lane];
        if (lane < 16) {
            float4 v = *(const float4*)(wv + brow*AA + lane*4);
            float* d2 = dst + 3 + lane*4;
            d2[0]=v.x; d2[1]=v.y; d2[2]=v.z; d2[3]=v.w;
        }
        if (KIN == 323) {
            #pragma unroll
            for (int q = 0; q < 2; q++) {
                float4 v = *(const float4*)(lower + brow*HH + (q*32+lane)*4);
                float* d2 = dst + 67 + (q*32+lane)*4;
                d2[0]=v.x; d2[1]=v.y; d2[2]=v.z; d2[3]=v.w;
            }
        }
        #pragma unroll
        for (int q = 0; q < 2; q++) {
            float4 v = *(const float4*)(hrec + brow*HH + (q*32+lane)*4);
            float* d2 = dst + KIN + (q*32+lane)*4;
            d2[0]=v.x; d2[1]=v.y; d2[2]=v.z; d2[3]=v.w;
        }
    }
}

// -------- GEMM tile (32 batch x 32 gate-cols) + LSTM cell update -------------
// thread (b = tid>>3, cq = tid&7) owns 4 consecutive cols of gate `cq>>1`.
template<int KIN>
__device__ __forceinline__ void lstm_gemm_update(
    const float* __restrict__ sX, float* __restrict__ sg,
    const float* __restrict__ Wih, const float* __restrict__ Whh,
    const float* __restrict__ bih, const float* __restrict__ bhh,
    float* __restrict__ cbuf, float* __restrict__ hout, int bb, int hb)
{
    const int Ktot = KIN + 256;
    int tid = threadIdx.x;
    int b = tid >> 3, cq = tid & 7;
    int gate = cq >> 1;
    int colbase = gate*HH + hb*8 + (cq & 1)*4;

    float b0 = bih[colbase+0] + bhh[colbase+0];
    float b1 = bih[colbase+1] + bhh[colbase+1];
    float b2 = bih[colbase+2] + bhh[colbase+2];
    float b3 = bih[colbase+3] + bhh[colbase+3];
    unsigned long long a01, a23;
    asm("mov.b64 %0, {%1, %2};" : "=l"(a01) : "f"(b0), "f"(b1));
    asm("mov.b64 %0, {%1, %2};" : "=l"(a23) : "f"(b2), "f"(b3));

    const float* xr = sX + b * Ktot;
    const char* wp = (const char*)Wih + (size_t)colbase * 4;
    #pragma unroll 4
    for (int k = 0; k < KIN; k++) {
        float xv = xr[k];
        ulonglong2 wv = *(const ulonglong2*)wp; wp += 4096;
        unsigned long long xx;
        asm("mov.b64 %0, {%1, %1};" : "=l"(xx) : "f"(xv));
        asm("fma.rn.f32x2 %0, %1, %2, %0;" : "+l"(a01) : "l"(wv.x), "l"(xx));
        asm("fma.rn.f32x2 %0, %1, %2, %0;" : "+l"(a23) : "l"(wv.y), "l"(xx));
    }
    const float* xr2 = xr + KIN;
    wp = (const char*)Whh + (size_t)colbase * 4;
    #pragma unroll 4
    for (int k = 0; k < 256; k++) {
        float xv = xr2[k];
        ulonglong2 wv = *(const ulonglong2*)wp; wp += 4096;
        unsigned long long xx;
        asm("mov.b64 %0, {%1, %1};" : "=l"(xx) : "f"(xv));
        asm("fma.rn.f32x2 %0, %1, %2, %0;" : "+l"(a01) : "l"(wv.x), "l"(xx));
        asm("fma.rn.f32x2 %0, %1, %2, %0;" : "+l"(a23) : "l"(wv.y), "l"(xx));
    }
    float f0,f1,f2,f3;
    asm("mov.b64 {%0, %1}, %2;" : "=f"(f0), "=f"(f1) : "l"(a01));
    asm("mov.b64 {%0, %1}, %2;" : "=f"(f2), "=f"(f3) : "l"(a23));
    float* sgr = sg + b*32 + cq*4;       // local col = gate*8 + hloc
    sgr[0]=f0; sgr[1]=f1; sgr[2]=f2; sgr[3]=f3;
    __syncthreads();

    // cell update: thread (ub = tid>>3, hl = tid&7)
    int ub = tid >> 3, hl = tid & 7;
    const float* row = sg + ub*32;
    float gi = row[hl], gf = row[8+hl], gg = row[16+hl], go = row[24+hl];
    int idx = (bb*32 + ub)*HH + hb*8 + hl;
    float i_ = sigmoidf_(gi);
    float f_ = sigmoidf_(gf);
    float g_ = tanhf(gg);
    float o_ = sigmoidf_(go);
    float cn = f_ * cbuf[idx] + i_ * g_;
    cbuf[idx] = cn;
    hout[idx] = o_ * tanhf(cn);
    __syncthreads();   // protect sg/sX before reuse
}

// -------- attention window phase: one batch row per CTA ----------------------
__device__ __forceinline__ void window_phase(const int* __restrict__ c,
                                             const float* __restrict__ Ww,
                                             const float* __restrict__ bw,
                                             const float* __restrict__ h1new,
                                             float* smem)
{
    float* sh1  = smem;            // 256
    float* swin = smem + 256;      // 30
    float* skap = smem + 286;      // 10
    float* sphi = smem + 296;      // 64
    int*   sci  = (int*)(smem + 360); // 64
    int b = blockIdx.x;
    int tid = threadIdx.x;

    sh1[tid] = h1new[b*HH + tid];
    __syncthreads();

    int j = tid >> 3, s = tid & 7;
    float p = 0.f;
    if (j < 30) {
        int k0 = s * 32;
        #pragma unroll
        for (int i = 0; i < 32; i++) p = fmaf(sh1[k0+i], Ww[(k0+i)*30 + j], p);
    }
    p += __shfl_down_sync(0xffffffffu, p, 4);
    p += __shfl_down_sync(0xffffffffu, p, 2);
    p += __shfl_down_sync(0xffffffffu, p, 1);
    if (j < 30 && s == 0) swin[j] = expf(p + bw[j]);
    __syncthreads();

    if (tid < KMIX) {
        float kn = fmaf(0.1f, swin[20 + tid], g_kappa[b*KMIX + tid]);
        g_kappa[b*KMIX + tid] = kn;
        skap[tid] = kn;
    }
    __syncthreads();

    if (tid < UU) {
        float u = (float)tid;
        float phi = 0.f;
        #pragma unroll
        for (int g = 0; g < KMIX; g++) {
            float d = skap[g] - u;
            phi = fmaf(swin[g], expf(-swin[10+g]*d*d), phi);
        }
        sphi[tid] = phi;
        sci[tid] = c[b*UU + tid];
    }
    __syncthreads();

    if (tid < AA) {
        float ws = 0.f;
        #pragma unroll 8
        for (int u = 0; u < UU; u++) ws += (sci[u] == tid) ? sphi[u] : 0.f;
        g_w[b*AA + tid] = ws;
    }
}

// -------- persistent scan kernel --------------------------------------------
__global__ void __launch_bounds__(NTHR, 1) scan_kernel(
    const float* __restrict__ x, const int* __restrict__ c,
    const float* __restrict__ Wih1, const float* __restrict__ Whh1,
    const float* __restrict__ bih1, const float* __restrict__ bhh1,
    const float* __restrict__ Wih2, const float* __restrict__ Whh2,
    const float* __restrict__ bih2, const float* __restrict__ bhh2,
    const float* __restrict__ Wih3, const float* __restrict__ Whh3,
    const float* __restrict__ bih3, const float* __restrict__ bhh3,
    const float* __restrict__ Ww,   const float* __restrict__ bw)
{
    extern __shared__ float smem[];
    float* sX = smem;
    float* sg = smem + 32*KT2;
    int tid = threadIdx.x;
    int bb = blockIdx.x & 3;
    int hb = blockIdx.x >> 2;

    // re-initialize recurrent state every launch (deterministic replays)
    {
        int gtid = blockIdx.x * NTHR + tid;          // 0..32767, == BN*HH
        g_h1[0][gtid] = 0.f; g_h2[0][gtid] = 0.f;
        g_c1[gtid] = 0.f; g_c2[gtid] = 0.f; g_c3[gtid] = 0.f;
        if (gtid < BN*AA)   g_w[gtid] = 1.0f;        // carry0: w = ones
        if (gtid < BN*KMIX) g_kappa[gtid] = 0.f;
    }
    grid_barrier();

    for (int t = 0; t < TT; t++) {
        const float* h1_old = g_h1[t & 1];
        float*       h1_new = g_h1[(t + 1) & 1];
        const float* h2_old = g_h2[t & 1];
        float*       h2_new = g_h2[(t + 1) & 1];

        // P1: LSTM1  (input [xt, w_prev], recur h1_old)
        load_rows<67>(sX, x, t, g_w, nullptr, h1_old, bb);
        __syncthreads();
        lstm_gemm_update<67>(sX, sg, Wih1, Whh1, bih1, bhh1, g_c1, h1_new, bb, hb);
        grid_barrier();

        // P2: attention window -> g_w, g_kappa
        window_phase(c, Ww, bw, h1_new, smem);
        grid_barrier();

        // P3: LSTM2  (input [xt, w, h1_new], recur h2_old)
        load_rows<323>(sX, x, t, g_w, h1_new, h2_old, bb);
        __syncthreads();
        lstm_gemm_update<323>(sX, sg, Wih2, Whh2, bih2, bhh2, g_c2, h2_new, bb, hb);
        grid_barrier();

        // P4: LSTM3  (input [xt, w, h2_new], recur h3_prev) -> g_out_h3[t]
        const float* h3prev = t ? (g_out_h3 + (size_t)(t-1)*BN*HH) : g_zero;
        load_rows<323>(sX, x, t, g_w, h2_new, h3prev, bb);
        __syncthreads();
        lstm_gemm_update<323>(sX, sg, Wih3, Whh3, bih3, bhh3, g_c3,
                              g_out_h3 + (size_t)t*BN*HH, bb, hb);
        // no barrier needed here (P1(t+1) touches disjoint state)
    }
}

// -------- MDN heads ----------------------------------------------------------
__global__ void __launch_bounds__(128) heads_kernel(
    const float* __restrict__ We,   const float* __restrict__ be,
    const float* __restrict__ Wpi,  const float* __restrict__ bpi,
    const float* __restrict__ Wmu1, const float* __restrict__ bmu1,
    const float* __restrict__ Wmu2, const float* __restrict__ bmu2,
    const float* __restrict__ Ws1,  const float* __restrict__ bs1,
    const float* __restrict__ Ws2,  const float* __restrict__ bs2,
    const float* __restrict__ Wrho, const float* __restrict__ brho,
    float* __restrict__ out)
{
    __shared__ float sh[HH];
    __shared__ float slog[GG];
    const int TB = TT * BN;
    int r = blockIdx.x;
    int tid = threadIdx.x;
    const float* h3 = g_out_h3 + (size_t)r * HH;
    if (tid < 64) ((float4*)sh)[tid] = ((const float4*)h3)[tid];
    __syncthreads();

    if (tid == 0) {
        float d = be[0];
        #pragma unroll 4
        for (int k = 0; k < HH; k++) d = fmaf(sh[k], We[k], d);
        out[r] = 1.0f / (1.0f + expf(d));                 // es
    } else if (tid <= 120) {
        int idx = tid - 1;
        int head = idx / GG, g = idx % GG;
        const float* W; const float* bv;
        switch (head) {
            case 0: W = Wpi;  bv = bpi;  break;
            case 1: W = Wmu1; bv = bmu1; break;
            case 2: W = Wmu2; bv = bmu2; break;
            case 3: W = Ws1;  bv = bs1;  break;
            case 4: W = Ws2;  bv = bs2;  break;
            default:W = Wrho; bv = brho; break;
        }
        float d = bv[g];
        #pragma unroll 4
        for (int k = 0; k < HH; k++) d = fmaf(sh[k], W[k*GG + g], d);
        if      (head == 0) slog[g] = d;                          // pi logits
        else if (head == 1) out[TB + 1*TB*GG + r*GG + g] = d;     // mu1
        else if (head == 2) out[TB + 2*TB*GG + r*GG + g] = d;     // mu2
        else if (head == 3) out[TB + 3*TB*GG + r*GG + g] = expf(d); // sigma1
        else if (head == 4) out[TB + 4*TB*GG + r*GG + g] = expf(d); // sigma2
        else                out[TB + 5*TB*GG + r*GG + g] = tanhf(d); // rho
    }
    __syncthreads();

    if (tid >= 1 && tid <= GG) {
        int g = tid - 1;
        float m = slog[0];
        #pragma unroll
        for (int i = 1; i < GG; i++) m = fmaxf(m, slog[i]);
        float ssum = 0.f;
        #pragma unroll
        for (int i = 0; i < GG; i++) ssum += expf(slog[i] - m);
        out[TB + r*GG + g] = expf(slog[g] - m) / ssum;            // pis
    }
}

// -------- launch -------------------------------------------------------------
extern "C" void kernel_launch(void* const* d_in, const int* in_sizes, int n_in,
                              void* d_out, int out_size) {
    const float* x    = (const float*)d_in[0];
    const int*   c    = (const int*)  d_in[1];
    const float* Wih1 = (const float*)d_in[2];
    const float* Whh1 = (const float*)d_in[3];
    const float* bih1 = (const float*)d_in[4];
    const float* bhh1 = (const float*)d_in[5];
    const float* Wih2 = (const float*)d_in[6];
    const float* Whh2 = (const float*)d_in[7];
    const float* bih2 = (const float*)d_in[8];
    const float* bhh2 = (const float*)d_in[9];
    const float* Wih3 = (const float*)d_in[10];
    const float* Whh3 = (const float*)d_in[11];
    const float* bih3 = (const float*)d_in[12];
    const float* bhh3 = (const float*)d_in[13];
    const float* Ww   = (const float*)d_in[14];
    const float* bw   = (const float*)d_in[15];
    const float* We   = (const float*)d_in[16];
    const float* be   = (const float*)d_in[17];
    const float* Wpi  = (const float*)d_in[18];
    const float* bpi  = (const float*)d_in[19];
    const float* Wmu1 = (const float*)d_in[20];
    const float* bmu1 = (const float*)d_in[21];
    const float* Wmu2 = (const float*)d_in[22];
    const float* bmu2 = (const float*)d_in[23];
    const float* Ws1  = (const float*)d_in[24];
    const float* bs1  = (const float*)d_in[25];
    const float* Ws2  = (const float*)d_in[26];
    const float* bs2  = (const float*)d_in[27];
    const float* Wrho = (const float*)d_in[28];
    const float* brho = (const float*)d_in[29];

    cudaFuncSetAttribute(scan_kernel, cudaFuncAttributeMaxDynamicSharedMemorySize, SMEM_BYTES);

    scan_kernel<<<NBLK, NTHR, SMEM_BYTES>>>(x, c,
        Wih1, Whh1, bih1, bhh1,
        Wih2, Whh2, bih2, bhh2,
        Wih3, Whh3, bih3, bhh3,
        Ww, bw);

    heads_kernel<<<TT*BN, 128>>>(We, be, Wpi, bpi, Wmu1, bmu1, Wmu2, bmu2,
                                 Ws1, bs1, Ws2, bs2, Wrho, brho, (float*)d_out);
}

// round 3
// speedup vs baseline: 2.6050x; 2.6050x over previous
#include <cuda_runtime.h>
#include <cuda_bf16.h>
#include <math.h>

// Problem dims
#define BN   128
#define TT   800
#define UU   64
#define HH   256
#define KMIX 10
#define GG   20
#define AA   64

#define NBLK 128
#define NTHR 256

// Unified feature order per LSTM: [w(64) | x(3) | h_seg(256) | h_seg(256)]
// LSTM1: Ktot=323 (one h segment), LSTM2/3: Ktot=579 (two h segments).

// ---- smem float offsets -----------------------------------------------------
#define OFF_W1 0
#define OFF_W2 (OFF_W1 + 323*16)
#define OFF_W3 (OFF_W2 + 579*16)
#define OFF_B  (OFF_W3 + 579*16)
#define OFF_E  (OFF_B  + 48)
#define OFF_H0 (OFF_E  + 64*68)
#define OFF_H1 (OFF_H0 + 64*68)
#define OFF_G  (OFF_H1 + 64*68)
#define SMEM_FLOATS (OFF_G + 64*20)
#define SMEM_BYTES  (SMEM_FLOATS*4)

// ---- persistent device state ------------------------------------------------
__device__ float g_h1[2][BN*HH];
__device__ float g_h2[2][BN*HH];
__device__ float g_w[BN*AA];
__device__ float g_kappa[BN*KMIX];
__device__ float g_zero[BN*HH];                 // never written (h3 at t=-1)
__device__ float g_out_h3[(size_t)TT*BN*HH];

__device__ unsigned g_bar_cnt;
__device__ volatile unsigned g_bar_gen;

// ---- software grid barrier (128 CTAs, 1/SM, all resident) -------------------
__device__ __forceinline__ void grid_barrier() {
    __syncthreads();
    if (threadIdx.x == 0) {
        unsigned gen = g_bar_gen;
        __threadfence();
        if (atomicAdd(&g_bar_cnt, 1u) == (unsigned)(gridDim.x - 1u)) {
            g_bar_cnt = 0u;
            __threadfence();
            g_bar_gen = gen + 1u;
        } else {
            while (g_bar_gen == gen) { }
        }
        __threadfence();
    }
    __syncthreads();
}

// ---- weight preload: [Ktot x 16] slice, gate-major 4-col groups -------------
__device__ __forceinline__ void load_w(float* wS, const float* __restrict__ Wih,
                                       const float* __restrict__ Whh,
                                       int KIN, int Ktot, int hs) {
    int tid = threadIdx.x;
    for (int idx = tid; idx < Ktot*4; idx += NTHR) {
        int k = idx >> 2, g = idx & 3;
        const float* src;
        if (k < 64)        src = Wih + (size_t)(3 + k) * 1024;   // w part
        else if (k < 67)   src = Wih + (size_t)(k - 64) * 1024;  // x part
        else if (k < KIN)  src = Wih + (size_t)k * 1024;         // h_lower (LSTM2/3)
        else               src = Whh + (size_t)(k - KIN) * 1024; // recurrent
        float4 v = *(const float4*)(src + g*HH + hs*4);
        *(float4*)(wS + k*16 + g*4) = v;
    }
}

// ---- staging helpers --------------------------------------------------------
__device__ __forceinline__ void stage_seg0(float* sE, const float* __restrict__ x,
                                           int t, int bg) {
    int tid = threadIdx.x;
    int r = tid >> 2, q = tid & 3;
    const float4* src = (const float4*)(g_w + (bg*64 + r)*AA) + q*4;
    float4* dst = (float4*)(sE + r*68) + q*4;
    dst[0]=src[0]; dst[1]=src[1]; dst[2]=src[2]; dst[3]=src[3];
    if (tid < 192) {
        int r2 = tid / 3, j = tid - r2*3;
        sE[r2*68 + 64 + j] = x[(size_t)(bg*64 + r2)*(TT*3) + t*3 + j];
    }
}

__device__ __forceinline__ void chunk_load(float4* v, const float* __restrict__ src,
                                           int bg, int hoff) {
    int tid = threadIdx.x;
    int r = tid >> 2, q = tid & 3;
    const float4* s = (const float4*)(src + (bg*64 + r)*HH + hoff) + q*4;
    v[0]=s[0]; v[1]=s[1]; v[2]=s[2]; v[3]=s[3];
}

__device__ __forceinline__ void chunk_store(float* dst, const float4* v) {
    int tid = threadIdx.x;
    int r = tid >> 2, q = tid & 3;
    float4* d = (float4*)(dst + r*68) + q*4;
    d[0]=v[0]; d[1]=v[1]; d[2]=v[2]; d[3]=v[3];
}

// ---- GEMM over one staged segment ------------------------------------------
__device__ __forceinline__ void gemm_seg(const float* __restrict__ xr,
                                         const float* __restrict__ wk, int nk,
                                         unsigned long long& a01, unsigned long long& a23) {
    #pragma unroll 4
    for (int k = 0; k < nk; k++) {
        float xv = xr[k];
        ulonglong2 wv = *(const ulonglong2*)(wk + k*16);
        unsigned long long xx;
        asm("mov.b64 %0, {%1, %1};" : "=l"(xx) : "f"(xv));
        asm("fma.rn.f32x2 %0, %1, %2, %0;" : "+l"(a01) : "l"(wv.x), "l"(xx));
        asm("fma.rn.f32x2 %0, %1, %2, %0;" : "+l"(a23) : "l"(wv.y), "l"(xx));
    }
}

// ---- one LSTM phase: stage -> GEMM -> cell update ---------------------------
// NC = number of 64-wide h chunks (4 for LSTM1, 8 for LSTM2/3)
template<int NC>
__device__ __forceinline__ void lstm_phase(
    float* smem, const float* __restrict__ wS, const float* __restrict__ sB,
    const float* __restrict__ x, int t, int bg, int hs,
    const float* __restrict__ segA, const float* __restrict__ segB,
    float& creg, float* __restrict__ hout)
{
    float* sE  = smem + OFF_E;
    float* sHa = smem + OFF_H0;
    float* sHb = smem + OFF_H1;
    float* sg  = smem + OFF_G;
    int tid = threadIdx.x;
    int b = tid >> 2, g = tid & 3;

    stage_seg0(sE, x, t, bg);
    { float4 v[4]; chunk_load(v, segA, bg, 0); chunk_store(sHa, v); }

    ulonglong2 bias = *(const ulonglong2*)(sB + g*4);
    unsigned long long a01 = bias.x, a23 = bias.y;

    __syncthreads();

    const float* wk = wS + g*4;

    float4 pf[4];
    chunk_load(pf, segA, bg, 64);                      // prefetch chunk 1
    gemm_seg(sE + b*68, wk, 67, a01, a23);             // seg0 (w|x)
    gemm_seg(sHa + b*68, wk + 67*16, 64, a01, a23);    // chunk 0

    #pragma unroll
    for (int c = 1; c < NC; c++) {
        float* buf = (c & 1) ? sHb : sHa;
        chunk_store(buf, pf);
        __syncthreads();
        if (c + 1 < NC) {
            const float* src = (c + 1 < 4) ? segA : segB;
            chunk_load(pf, src, bg, ((c + 1) & 3) * 64);
        }
        gemm_seg(buf + b*68, wk + (67 + c*64)*16, 64, a01, a23);
    }

    float f0,f1,f2,f3;
    asm("mov.b64 {%0,%1}, %2;" : "=f"(f0), "=f"(f1) : "l"(a01));
    asm("mov.b64 {%0,%1}, %2;" : "=f"(f2), "=f"(f3) : "l"(a23));
    *(float4*)(sg + b*20 + g*4) = make_float4(f0, f1, f2, f3);
    __syncthreads();

    // cell update: thread (b, hl=g) owns hidden unit hs*4+hl for batch row b
    int hl = g;
    const float* row = sg + b*20;
    float gi = row[hl], gf = row[4+hl], gz = row[8+hl], go = row[12+hl];
    float i_ = 1.0f / (1.0f + expf(-gi));
    float f_ = 1.0f / (1.0f + expf(-gf));
    float z_ = tanhf(gz);
    float o_ = 1.0f / (1.0f + expf(-go));
    float cn = f_ * creg + i_ * z_;
    creg = cn;
    hout[(bg*64 + b)*HH + hs*4 + hl] = o_ * tanhf(cn);
}

// ---- attention window phase: one batch row per CTA --------------------------
__device__ __forceinline__ void window_phase(const int* __restrict__ cseq,
                                             const float* __restrict__ Ww,
                                             const float* __restrict__ bw,
                                             const float* __restrict__ h1new,
                                             float* smem)
{
    float* sh1  = smem;              // 256
    float* swin = smem + 256;        // 30
    float* skap = smem + 286;        // 10
    float* sphi = smem + 296;        // 64
    int*   sci  = (int*)(smem + 360);// 64
    int b = blockIdx.x;
    int tid = threadIdx.x;

    sh1[tid] = h1new[b*HH + tid];
    __syncthreads();

    int j = tid >> 3, s = tid & 7;
    float p = 0.f;
    if (j < 30) {
        int k0 = s * 32;
        #pragma unroll
        for (int i = 0; i < 32; i++) p = fmaf(sh1[k0+i], Ww[(k0+i)*30 + j], p);
    }
    p += __shfl_down_sync(0xffffffffu, p, 4);
    p += __shfl_down_sync(0xffffffffu, p, 2);
    p += __shfl_down_sync(0xffffffffu, p, 1);
    if (j < 30 && s == 0) swin[j] = expf(p + bw[j]);
    __syncthreads();

    if (tid < KMIX) {
        float kn = fmaf(0.1f, swin[20 + tid], g_kappa[b*KMIX + tid]);
        g_kappa[b*KMIX + tid] = kn;
        skap[tid] = kn;
    }
    __syncthreads();

    if (tid < UU) {
        float u = (float)tid;
        float phi = 0.f;
        #pragma unroll
        for (int g = 0; g < KMIX; g++) {
            float d = skap[g] - u;
            phi = fmaf(swin[g], expf(-swin[10+g]*d*d), phi);
        }
        sphi[tid] = phi;
        sci[tid] = cseq[b*UU + tid];
    }
    __syncthreads();

    if (tid < AA) {
        float ws = 0.f;
        #pragma unroll 8
        for (int u = 0; u < UU; u++) ws += (sci[u] == tid) ? sphi[u] : 0.f;
        g_w[b*AA + tid] = ws;
    }
}

// ---- persistent scan kernel -------------------------------------------------
__global__ void __launch_bounds__(NTHR, 1) scan_kernel(
    const float* __restrict__ x, const int* __restrict__ cseq,
    const float* __restrict__ Wih1, const float* __restrict__ Whh1,
    const float* __restrict__ bih1, const float* __restrict__ bhh1,
    const float* __restrict__ Wih2, const float* __restrict__ Whh2,
    const float* __restrict__ bih2, const float* __restrict__ bhh2,
    const float* __restrict__ Wih3, const float* __restrict__ Whh3,
    const float* __restrict__ bih3, const float* __restrict__ bhh3,
    const float* __restrict__ Ww,   const float* __restrict__ bw)
{
    extern __shared__ float smem[];
    int tid = threadIdx.x;
    int bg = blockIdx.x >> 6;        // 0..1: batch group of 64 rows
    int hs = blockIdx.x & 63;        // 0..63: 4 hidden units each

    // one-time: weights + bias sums into smem
    load_w(smem + OFF_W1, Wih1, Whh1, 67,  323, hs);
    load_w(smem + OFF_W2, Wih2, Whh2, 323, 579, hs);
    load_w(smem + OFF_W3, Wih3, Whh3, 323, 579, hs);
    if (tid < 48) {
        int l = tid >> 4, c16 = tid & 15;
        int g = c16 >> 2, hl = c16 & 3;
        int gc = g*HH + hs*4 + hl;
        const float* bi = (l == 0) ? bih1 : ((l == 1) ? bih2 : bih3);
        const float* bh = (l == 0) ? bhh1 : ((l == 1) ? bhh2 : bhh3);
        smem[OFF_B + tid] = bi[gc] + bh[gc];
    }
    // re-init persistent state (deterministic replays)
    {
        int gtid = blockIdx.x * NTHR + tid;          // covers BN*HH = 32768
        g_h1[0][gtid] = 0.f; g_h2[0][gtid] = 0.f;
        if (gtid < BN*AA)   g_w[gtid] = 1.0f;
        if (gtid < BN*KMIX) g_kappa[gtid] = 0.f;
    }
    float c1 = 0.f, c2 = 0.f, c3 = 0.f;
    __syncthreads();
    grid_barrier();

    for (int t = 0; t < TT; t++) {
        float* h1o = g_h1[t & 1];
        float* h1n = g_h1[(t + 1) & 1];
        float* h2o = g_h2[t & 1];
        float* h2n = g_h2[(t + 1) & 1];

        // P1: LSTM1  features [w(t-1), x(t), h1(t-1)]
        lstm_phase<4>(smem, smem + OFF_W1, smem + OFF_B, x, t, bg, hs,
                      h1o, nullptr, c1, h1n);
        grid_barrier();

        // P2: attention window -> g_w, g_kappa
        window_phase(cseq, Ww, bw, h1n, smem + OFF_E);
        grid_barrier();

        // P3: LSTM2  features [w(t), x(t), h1(t), h2(t-1)]
        lstm_phase<8>(smem, smem + OFF_W2, smem + OFF_B + 16, x, t, bg, hs,
                      h1n, h2o, c2, h2n);
        grid_barrier();

        // P4: LSTM3  features [w(t), x(t), h2(t), h3(t-1)] -> g_out_h3[t]
        const float* h3p = t ? (g_out_h3 + (size_t)(t-1)*BN*HH) : g_zero;
        lstm_phase<8>(smem, smem + OFF_W3, smem + OFF_B + 32, x, t, bg, hs,
                      h2n, h3p, c3, g_out_h3 + (size_t)t*BN*HH);
        // no barrier: P1(t+1) touches disjoint state (h1 bufs, g_w stable)
    }
}

// ---- MDN heads --------------------------------------------------------------
__global__ void __launch_bounds__(128) heads_kernel(
    const float* __restrict__ We,   const float* __restrict__ be,
    const float* __restrict__ Wpi,  const float* __restrict__ bpi,
    const float* __restrict__ Wmu1, const float* __restrict__ bmu1,
    const float* __restrict__ Wmu2, const float* __restrict__ bmu2,
    const float* __restrict__ Ws1,  const float* __restrict__ bs1,
    const float* __restrict__ Ws2,  const float* __restrict__ bs2,
    const float* __restrict__ Wrho, const float* __restrict__ brho,
    float* __restrict__ out)
{
    __shared__ float sh[HH];
    __shared__ float slog[GG];
    const int TB = TT * BN;
    int r = blockIdx.x;
    int tid = threadIdx.x;
    const float* h3 = g_out_h3 + (size_t)r * HH;
    if (tid < 64) ((float4*)sh)[tid] = ((const float4*)h3)[tid];
    __syncthreads();

    if (tid == 0) {
        float d = be[0];
        #pragma unroll 4
        for (int k = 0; k < HH; k++) d = fmaf(sh[k], We[k], d);
        out[r] = 1.0f / (1.0f + expf(d));
    } else if (tid <= 120) {
        int idx = tid - 1;
        int head = idx / GG, g = idx % GG;
        const float* W; const float* bv;
        switch (head) {
            case 0: W = Wpi;  bv = bpi;  break;
            case 1: W = Wmu1; bv = bmu1; break;
            case 2: W = Wmu2; bv = bmu2; break;
            case 3: W = Ws1;  bv = bs1;  break;
            case 4: W = Ws2;  bv = bs2;  break;
            default:W = Wrho; bv = brho; break;
        }
        float d = bv[g];
        #pragma unroll 4
        for (int k = 0; k < HH; k++) d = fmaf(sh[k], W[k*GG + g], d);
        if      (head == 0) slog[g] = d;
        else if (head == 1) out[TB + 1*TB*GG + r*GG + g] = d;
        else if (head == 2) out[TB + 2*TB*GG + r*GG + g] = d;
        else if (head == 3) out[TB + 3*TB*GG + r*GG + g] = expf(d);
        else if (head == 4) out[TB + 4*TB*GG + r*GG + g] = expf(d);
        else                out[TB + 5*TB*GG + r*GG + g] = tanhf(d);
    }
    __syncthreads();

    if (tid >= 1 && tid <= GG) {
        int g = tid - 1;
        float m = slog[0];
        #pragma unroll
        for (int i = 1; i < GG; i++) m = fmaxf(m, slog[i]);
        float ssum = 0.f;
        #pragma unroll
        for (int i = 0; i < GG; i++) ssum += expf(slog[i] - m);
        out[TB + r*GG + g] = expf(slog[g] - m) / ssum;
    }
}

// ---- launch -----------------------------------------------------------------
extern "C" void kernel_launch(void* const* d_in, const int* in_sizes, int n_in,
                              void* d_out, int out_size) {
    const float* x    = (const float*)d_in[0];
    const int*   cs   = (const int*)  d_in[1];
    const float* Wih1 = (const float*)d_in[2];
    const float* Whh1 = (const float*)d_in[3];
    const float* bih1 = (const float*)d_in[4];
    const float* bhh1 = (const float*)d_in[5];
    const float* Wih2 = (const float*)d_in[6];
    const float* Whh2 = (const float*)d_in[7];
    const float* bih2 = (const float*)d_in[8];
    const float* bhh2 = (const float*)d_in[9];
    const float* Wih3 = (const float*)d_in[10];
    const float* Whh3 = (const float*)d_in[11];
    const float* bih3 = (const float*)d_in[12];
    const float* bhh3 = (const float*)d_in[13];
    const float* Ww   = (const float*)d_in[14];
    const float* bw   = (const float*)d_in[15];
    const float* We   = (const float*)d_in[16];
    const float* be   = (const float*)d_in[17];
    const float* Wpi  = (const float*)d_in[18];
    const float* bpi  = (const float*)d_in[19];
    const float* Wmu1 = (const float*)d_in[20];
    const float* bmu1 = (const float*)d_in[21];
    const float* Wmu2 = (const float*)d_in[22];
    const float* bmu2 = (const float*)d_in[23];
    const float* Ws1  = (const float*)d_in[24];
    const float* bs1  = (const float*)d_in[25];
    const float* Ws2  = (const float*)d_in[26];
    const float* bs2  = (const float*)d_in[27];
    const float* Wrho = (const float*)d_in[28];
    const float* brho = (const float*)d_in[29];

    cudaFuncSetAttribute(scan_kernel, cudaFuncAttributeMaxDynamicSharedMemorySize, SMEM_BYTES);

    scan_kernel<<<NBLK, NTHR, SMEM_BYTES>>>(x, cs,
        Wih1, Whh1, bih1, bhh1,
        Wih2, Whh2, bih2, bhh2,
        Wih3, Whh3, bih3, bhh3,
        Ww, bw);

    heads_kernel<<<TT*BN, 128>>>(We, be, Wpi, bpi, Wmu1, bmu1, Wmu2, bmu2,
                                 Ws1, bs1, Ws2, bs2, Wrho, brho, (float*)d_out);
}